// round 1
// baseline (speedup 1.0000x reference)
#include <cuda_runtime.h>
#include <cuda_bf16.h>
#include <math.h>

#define NB 4
#define TT 2048
#define DM 512
#define NH 8
#define HD 64
#define PAD 65
#define SCALE 0.125f

// Scratch (no allocation allowed): head-major q/k/v, token-major ctx.
__device__ float g_q[NB * NH * TT * HD];
__device__ float g_k[NB * NH * TT * HD];
__device__ float g_v[NB * NH * TT * HD];
__device__ float g_ctx[NB * TT * DM];

// ---------------------------------------------------------------------------
// GEMM1: qkv[m][e] = sum_k x[m][k] * Wqkv[e][k]   (M=8192, E=1536, K=512)
// Block tile 128(m) x 64(e), 256 threads, 8x4 micro-tile, K-chunk 32.
// Epilogue scatters into head-major g_q/g_k/g_v.
// ---------------------------------------------------------------------------
__global__ void __launch_bounds__(256) qkv_kernel(const float* __restrict__ x,
                                                  const float* __restrict__ w) {
    const int e0 = blockIdx.x * 64;
    const int m0 = blockIdx.y * 128;
    __shared__ float xs[32][129];  // [k][m], pad -> conflict-free stores & reads
    __shared__ float ws[32][65];   // [k][e]

    const int tid = threadIdx.x;
    const int tx = tid & 15;       // e direction (4 cols)
    const int ty = tid >> 4;       // m direction (8 rows)

    float acc[8][4];
#pragma unroll
    for (int i = 0; i < 8; i++)
#pragma unroll
        for (int j = 0; j < 4; j++) acc[i][j] = 0.f;

    for (int kc = 0; kc < 512; kc += 32) {
#pragma unroll
        for (int i = 0; i < 16; i++) {
            int elem = tid + i * 256;           // 128*32 = 4096
            int mr = elem >> 5, kr = elem & 31;
            xs[kr][mr] = x[(m0 + mr) * 512 + kc + kr];
        }
#pragma unroll
        for (int i = 0; i < 8; i++) {
            int elem = tid + i * 256;           // 64*32 = 2048
            int er = elem >> 5, kr = elem & 31;
            ws[kr][er] = w[(e0 + er) * 512 + kc + kr];
        }
        __syncthreads();
#pragma unroll
        for (int k = 0; k < 32; k++) {
            float a[8], b[4];
#pragma unroll
            for (int i = 0; i < 8; i++) a[i] = xs[k][ty * 8 + i];
#pragma unroll
            for (int j = 0; j < 4; j++) b[j] = ws[k][tx * 4 + j];
#pragma unroll
            for (int i = 0; i < 8; i++)
#pragma unroll
                for (int j = 0; j < 4; j++) acc[i][j] = fmaf(a[i], b[j], acc[i][j]);
        }
        __syncthreads();
    }

#pragma unroll
    for (int i = 0; i < 8; i++) {
        int m = m0 + ty * 8 + i;
        int n = m >> 11;        // / 2048
        int t = m & 2047;
#pragma unroll
        for (int j = 0; j < 4; j++) {
            int e = e0 + tx * 4 + j;
            int sec = e >> 9;           // 0=q 1=k 2=v
            int h = (e >> 6) & 7;
            int d = e & 63;
            float* buf = (sec == 0) ? g_q : (sec == 1) ? g_k : g_v;
            buf[(((size_t)(n * NH + h)) * TT + t) * HD + d] = acc[i][j];
        }
    }
}

// ---------------------------------------------------------------------------
// RoPE in place on g_q and g_k. One warp per (n,h,t) row. lane owns (d, d+32).
// ---------------------------------------------------------------------------
__global__ void __launch_bounds__(256) rope_kernel() {
    int widx = blockIdx.x * 8 + (threadIdx.x >> 5);
    if (widx >= NB * NH * TT) return;
    int lane = threadIdx.x & 31;
    int t = widx & (TT - 1);    // layout [(n,h)][t][d]
    size_t base = (size_t)widx * HD;

    // inv_freq[lane] = 10000^{-2*lane/64}; angle in double for accurate trig.
    double inv_freq = pow(10000.0, -((double)(2 * lane) / 64.0));
    // match reference: angle is the fp32 product t * inv_freq_fp32
    float ang = (float)t * (float)inv_freq;
    float c = (float)cos((double)ang);
    float s = (float)sin((double)ang);

    float q1 = g_q[base + lane], q2 = g_q[base + lane + 32];
    g_q[base + lane]      = q1 * c - q2 * s;
    g_q[base + lane + 32] = q2 * c + q1 * s;

    float k1 = g_k[base + lane], k2 = g_k[base + lane + 32];
    g_k[base + lane]      = k1 * c - k2 * s;
    g_k[base + lane + 32] = k2 * c + k1 * s;
}

// ---------------------------------------------------------------------------
// Sliding-window attention: block = (qtile, h, n); 64 queries; key chunks of 64
// over [qtile-2, qtile+2]; online softmax; ctx written token-major.
// ---------------------------------------------------------------------------
__global__ void __launch_bounds__(256) attn_kernel() {
    extern __shared__ float sh[];
    float* q_sh = sh;                    // 64 * PAD
    float* k_sh = sh + 64 * PAD;
    float* v_sh = sh + 2 * 64 * PAD;
    float* p_sh = sh + 3 * 64 * PAD;

    const int qt = blockIdx.x;
    const int h = blockIdx.y;
    const int n = blockIdx.z;
    const int q0 = qt * 64;
    const int tid = threadIdx.x;
    const int w = tid >> 5;
    const int lane = tid & 31;

    const size_t hb = ((size_t)(n * NH + h)) * TT * HD;
    const float* qg = g_q + hb;
    const float* kg = g_k + hb;
    const float* vg = g_v + hb;

    // load Q tile
#pragma unroll
    for (int i = 0; i < 16; i++) {
        int elem = tid + i * 256;
        int r = elem >> 6, d = elem & 63;
        q_sh[r * PAD + d] = qg[(q0 + r) * HD + d];
    }

    float m_i[8], l_i[8], acc0[8], acc1[8];
#pragma unroll
    for (int rr = 0; rr < 8; rr++) {
        m_i[rr] = -1e30f; l_i[rr] = 0.f; acc0[rr] = 0.f; acc1[rr] = 0.f;
    }

    int c0 = qt - 2; if (c0 < 0) c0 = 0;
    int c1 = qt + 2; if (c1 > TT / 64 - 1) c1 = TT / 64 - 1;

    __syncthreads();

    for (int c = c0; c <= c1; c++) {
        const int j0 = c * 64;
#pragma unroll
        for (int i = 0; i < 16; i++) {
            int elem = tid + i * 256;
            int r = elem >> 6, d = elem & 63;
            k_sh[r * PAD + d] = kg[(j0 + r) * HD + d];
            v_sh[r * PAD + d] = vg[(j0 + r) * HD + d];
        }
        __syncthreads();

        // ---- scores: s[rr] = q[row] . k[lane(+32)] ----
        float s0[8], s1[8];
#pragma unroll
        for (int rr = 0; rr < 8; rr++) { s0[rr] = 0.f; s1[rr] = 0.f; }
#pragma unroll
        for (int d = 0; d < 64; d++) {
            float k0 = k_sh[lane * PAD + d];
            float k1 = k_sh[(lane + 32) * PAD + d];
#pragma unroll
            for (int rr = 0; rr < 8; rr++) {
                float qv = q_sh[(w * 8 + rr) * PAD + d];
                s0[rr] = fmaf(qv, k0, s0[rr]);
                s1[rr] = fmaf(qv, k1, s1[rr]);
            }
        }

        // ---- mask + online softmax update ----
#pragma unroll
        for (int rr = 0; rr < 8; rr++) {
            int ig = q0 + w * 8 + rr;
            int jg0 = j0 + lane;
            int jg1 = j0 + lane + 32;
            bool v0 = (jg0 >= ig - 127) && (jg0 <= ig + 128);
            bool v1 = (jg1 >= ig - 127) && (jg1 <= ig + 128);
            float t0 = v0 ? s0[rr] * SCALE : -1e30f;
            float t1 = v1 ? s1[rr] * SCALE : -1e30f;
            float mx = fmaxf(t0, t1);
#pragma unroll
            for (int off = 16; off > 0; off >>= 1)
                mx = fmaxf(mx, __shfl_xor_sync(0xffffffffu, mx, off));
            float m_new = fmaxf(m_i[rr], mx);
            float p0 = v0 ? expf(t0 - m_new) : 0.f;
            float p1 = v1 ? expf(t1 - m_new) : 0.f;
            float ps = p0 + p1;
#pragma unroll
            for (int off = 16; off > 0; off >>= 1)
                ps += __shfl_xor_sync(0xffffffffu, ps, off);
            float alpha = expf(m_i[rr] - m_new);
            l_i[rr] = l_i[rr] * alpha + ps;
            acc0[rr] *= alpha;
            acc1[rr] *= alpha;
            m_i[rr] = m_new;
            p_sh[(w * 8 + rr) * PAD + lane] = p0;
            p_sh[(w * 8 + rr) * PAD + lane + 32] = p1;
        }
        __syncwarp();

        // ---- PV: acc[rr][d] += sum_col p[rr][col] * v[col][d] ----
#pragma unroll 4
        for (int col = 0; col < 64; col++) {
            float v0 = v_sh[col * PAD + lane];
            float v1 = v_sh[col * PAD + lane + 32];
#pragma unroll
            for (int rr = 0; rr < 8; rr++) {
                float p = p_sh[(w * 8 + rr) * PAD + col];
                acc0[rr] = fmaf(p, v0, acc0[rr]);
                acc1[rr] = fmaf(p, v1, acc1[rr]);
            }
        }
        __syncthreads();
    }

    // ---- write ctx, token-major [n][t][h*64+d] ----
#pragma unroll
    for (int rr = 0; rr < 8; rr++) {
        int ig = q0 + w * 8 + rr;
        float invl = 1.f / l_i[rr];
        size_t o = ((size_t)n * TT + ig) * DM + h * HD;
        g_ctx[o + lane] = acc0[rr] * invl;
        g_ctx[o + lane + 32] = acc1[rr] * invl;
    }
}

// ---------------------------------------------------------------------------
// GEMM2: out[m][e] = sum_k ctx[m][k] * out_w[e][k] + out_b[e]  (E=512, K=512)
// ---------------------------------------------------------------------------
__global__ void __launch_bounds__(256) out_kernel(const float* __restrict__ w,
                                                  const float* __restrict__ bias,
                                                  float* __restrict__ out) {
    const int e0 = blockIdx.x * 64;
    const int m0 = blockIdx.y * 128;
    __shared__ float xs[32][129];
    __shared__ float ws[32][65];

    const int tid = threadIdx.x;
    const int tx = tid & 15;
    const int ty = tid >> 4;

    float acc[8][4];
#pragma unroll
    for (int i = 0; i < 8; i++)
#pragma unroll
        for (int j = 0; j < 4; j++) acc[i][j] = 0.f;

    for (int kc = 0; kc < 512; kc += 32) {
#pragma unroll
        for (int i = 0; i < 16; i++) {
            int elem = tid + i * 256;
            int mr = elem >> 5, kr = elem & 31;
            xs[kr][mr] = g_ctx[(size_t)(m0 + mr) * 512 + kc + kr];
        }
#pragma unroll
        for (int i = 0; i < 8; i++) {
            int elem = tid + i * 256;
            int er = elem >> 5, kr = elem & 31;
            ws[kr][er] = w[(e0 + er) * 512 + kc + kr];
        }
        __syncthreads();
#pragma unroll
        for (int k = 0; k < 32; k++) {
            float a[8], b[4];
#pragma unroll
            for (int i = 0; i < 8; i++) a[i] = xs[k][ty * 8 + i];
#pragma unroll
            for (int j = 0; j < 4; j++) b[j] = ws[k][tx * 4 + j];
#pragma unroll
            for (int i = 0; i < 8; i++)
#pragma unroll
                for (int j = 0; j < 4; j++) acc[i][j] = fmaf(a[i], b[j], acc[i][j]);
        }
        __syncthreads();
    }

#pragma unroll
    for (int i = 0; i < 8; i++) {
        int m = m0 + ty * 8 + i;
#pragma unroll
        for (int j = 0; j < 4; j++) {
            int e = e0 + tx * 4 + j;
            out[(size_t)m * 512 + e] = acc[i][j] + bias[e];
        }
    }
}

// ---------------------------------------------------------------------------
extern "C" void kernel_launch(void* const* d_in, const int* in_sizes, int n_in,
                              void* d_out, int out_size) {
    const float* x    = (const float*)d_in[0];   // [4,2048,512]
    const float* wqkv = (const float*)d_in[1];   // [1536,512]
    const float* outw = (const float*)d_in[2];   // [512,512]
    const float* outb = (const float*)d_in[3];   // [512]
    float* out = (float*)d_out;

    const int att_smem = 4 * 64 * PAD * sizeof(float);  // 66560 B
    cudaFuncSetAttribute(attn_kernel, cudaFuncAttributeMaxDynamicSharedMemorySize,
                         att_smem);

    qkv_kernel<<<dim3(1536 / 64, 8192 / 128), 256>>>(x, wqkv);
    rope_kernel<<<(NB * NH * TT) / 8, 256>>>();
    attn_kernel<<<dim3(TT / 64, NH, NB), 256, att_smem>>>();
    out_kernel<<<dim3(512 / 64, 8192 / 128), 256>>>(outw, outb, out);
}

// round 2
// speedup vs baseline: 1.5503x; 1.5503x over previous
#include <cuda_runtime.h>
#include <math.h>

#define NB 4
#define TT 2048
#define DM 512
#define NH 8
#define HD 64
#define SCALE 0.125f

// Scratch (no allocation allowed)
__device__ float g_q[NB * NH * TT * HD];
__device__ float g_k[NB * NH * TT * HD];
__device__ float g_v[NB * NH * TT * HD];
__device__ float g_ctx[NB * TT * DM];

__device__ __forceinline__ unsigned f2tf(float x) {
    unsigned u;
    asm("cvt.rna.tf32.f32 %0, %1;" : "=r"(u) : "f"(x));
    return u;
}

__device__ __forceinline__ void mma8(float* c, const unsigned* a, const unsigned* b) {
    asm volatile(
        "mma.sync.aligned.m16n8k8.row.col.f32.tf32.tf32.f32 "
        "{%0,%1,%2,%3},{%4,%5,%6,%7},{%8,%9},{%0,%1,%2,%3};"
        : "+f"(c[0]), "+f"(c[1]), "+f"(c[2]), "+f"(c[3])
        : "r"(a[0]), "r"(a[1]), "r"(a[2]), "r"(a[3]), "r"(b[0]), "r"(b[1]));
}

// ---------------------------------------------------------------------------
// tf32 GEMM: C[m][e] = sum_k A[m][k] * W[e][k]
// Block tile 128m x 64e, 256 thr = 8 warps (4m x 2n), warp tile 32m x 32e.
// QKV=true: scatter into g_q/g_k/g_v. QKV=false: read g_ctx, write out+bias.
// ---------------------------------------------------------------------------
template <bool QKV>
__global__ void __launch_bounds__(256) gemm_tf32(const float* __restrict__ A,
                                                 const float* __restrict__ W,
                                                 const float* __restrict__ bias,
                                                 float* __restrict__ out) {
    __shared__ unsigned xs[128 * 36];
    __shared__ unsigned ws[64 * 36];

    const int e0 = blockIdx.x * 64;
    const int m0 = blockIdx.y * 128;
    const int tid = threadIdx.x;
    const int wid = tid >> 5, lane = tid & 31;
    const int wm = wid >> 1, wn = wid & 1;
    const int g = lane >> 2, t4 = lane & 3;

    const float* Ap = QKV ? A : (const float*)g_ctx;

    float acc[2][4][4];
#pragma unroll
    for (int mt = 0; mt < 2; mt++)
#pragma unroll
        for (int nt = 0; nt < 4; nt++)
#pragma unroll
            for (int r = 0; r < 4; r++) acc[mt][nt][r] = 0.f;

    for (int kc = 0; kc < 512; kc += 32) {
#pragma unroll
        for (int i = 0; i < 4; i++) {
            int idx = tid + i * 256;  // 1024: 128 rows x 8 float4
            int r = idx >> 3, k4 = idx & 7;
            float4 v = *(const float4*)(Ap + (size_t)(m0 + r) * 512 + kc + k4 * 4);
            unsigned* p = &xs[r * 36 + k4 * 4];
            p[0] = f2tf(v.x); p[1] = f2tf(v.y); p[2] = f2tf(v.z); p[3] = f2tf(v.w);
        }
#pragma unroll
        for (int i = 0; i < 2; i++) {
            int idx = tid + i * 256;  // 512: 64 rows x 8 float4
            int r = idx >> 3, k4 = idx & 7;
            float4 v = *(const float4*)(W + (size_t)(e0 + r) * 512 + kc + k4 * 4);
            unsigned* p = &ws[r * 36 + k4 * 4];
            p[0] = f2tf(v.x); p[1] = f2tf(v.y); p[2] = f2tf(v.z); p[3] = f2tf(v.w);
        }
        __syncthreads();

#pragma unroll
        for (int ks = 0; ks < 4; ks++) {
            unsigned a[2][4], b[4][2];
            const int col = ks * 8 + t4;
#pragma unroll
            for (int mt = 0; mt < 2; mt++) {
                int r = wm * 32 + mt * 16 + g;
                a[mt][0] = xs[r * 36 + col];
                a[mt][1] = xs[(r + 8) * 36 + col];
                a[mt][2] = xs[r * 36 + col + 4];
                a[mt][3] = xs[(r + 8) * 36 + col + 4];
            }
#pragma unroll
            for (int nt = 0; nt < 4; nt++) {
                int e = wn * 32 + nt * 8 + g;
                b[nt][0] = ws[e * 36 + col];
                b[nt][1] = ws[e * 36 + col + 4];
            }
#pragma unroll
            for (int mt = 0; mt < 2; mt++)
#pragma unroll
                for (int nt = 0; nt < 4; nt++) mma8(acc[mt][nt], a[mt], b[nt]);
        }
        __syncthreads();
    }

    if (QKV) {
        const int sec = e0 >> 9;
        const int h = (e0 >> 6) & 7;
        float* buf = (sec == 0) ? g_q : (sec == 1) ? g_k : g_v;
#pragma unroll
        for (int mt = 0; mt < 2; mt++)
#pragma unroll
            for (int half = 0; half < 2; half++) {
                int m = m0 + wm * 32 + mt * 16 + g + half * 8;
                int nbt = m >> 11, tt = m & 2047;
                size_t base = (((size_t)(nbt * NH + h)) * TT + tt) * HD;
#pragma unroll
                for (int nt = 0; nt < 4; nt++) {
                    int d = wn * 32 + nt * 8 + t4 * 2;
                    float2 v = make_float2(acc[mt][nt][half * 2], acc[mt][nt][half * 2 + 1]);
                    *(float2*)(buf + base + d) = v;
                }
            }
    } else {
#pragma unroll
        for (int mt = 0; mt < 2; mt++)
#pragma unroll
            for (int half = 0; half < 2; half++) {
                int m = m0 + wm * 32 + mt * 16 + g + half * 8;
#pragma unroll
                for (int nt = 0; nt < 4; nt++) {
                    int e = e0 + wn * 32 + nt * 8 + t4 * 2;
                    float2 bv = *(const float2*)(bias + e);
                    float2 v = make_float2(acc[mt][nt][half * 2] + bv.x,
                                           acc[mt][nt][half * 2 + 1] + bv.y);
                    *(float2*)(out + (size_t)m * 512 + e) = v;
                }
            }
    }
}

// ---------------------------------------------------------------------------
// RoPE in place on g_q and g_k. One warp per (n,h,t) row. lane owns (d, d+32).
// ---------------------------------------------------------------------------
__global__ void __launch_bounds__(256) rope_kernel() {
    int widx = blockIdx.x * 8 + (threadIdx.x >> 5);
    if (widx >= NB * NH * TT) return;
    int lane = threadIdx.x & 31;
    int t = widx & (TT - 1);
    size_t base = (size_t)widx * HD;

    double inv_freq = pow(10000.0, -((double)(2 * lane) / 64.0));
    float ang = (float)t * (float)inv_freq;
    float c = (float)cos((double)ang);
    float s = (float)sin((double)ang);

    float q1 = g_q[base + lane], q2 = g_q[base + lane + 32];
    g_q[base + lane]      = q1 * c - q2 * s;
    g_q[base + lane + 32] = q2 * c + q1 * s;

    float k1 = g_k[base + lane], k2 = g_k[base + lane + 32];
    g_k[base + lane]      = k1 * c - k2 * s;
    g_k[base + lane + 32] = k2 * c + k1 * s;
}

// ---------------------------------------------------------------------------
// Sliding-window attention, tf32 mma. Block = 128 q rows x (h, n).
// 8 warps, each warp owns 16 q rows. Key chunks of 64 over [2qt-2, 2qt+3].
// Q fragments register-resident; P goes through smem (reuses Q staging area).
// ---------------------------------------------------------------------------
__global__ void __launch_bounds__(256) attn_kernel() {
    extern __shared__ unsigned sh[];
    unsigned* qp = sh;                 // 128*68  (Q staging, then P)
    unsigned* ksh = sh + 128 * 68;     // 64*68   (K[key][dim])
    unsigned* vsh = ksh + 64 * 68;     // 64*68   (V[key][dim])

    const int qt = blockIdx.x;
    const int h = blockIdx.y;
    const int n = blockIdx.z;
    const int q0 = qt * 128;
    const int tid = threadIdx.x;
    const int wid = tid >> 5, lane = tid & 31;
    const int g = lane >> 2, t4 = lane & 3;

    const size_t hb = ((size_t)(n * NH + h)) * TT * HD;
    const float* qg = g_q + hb;
    const float* kg = g_k + hb;
    const float* vg = g_v + hb;

    // stage Q (tf32-converted)
#pragma unroll
    for (int i = 0; i < 8; i++) {
        int idx = tid + i * 256;  // 2048: 128 rows x 16 float4
        int r = idx >> 4, d4 = idx & 15;
        float4 v = *(const float4*)(qg + (size_t)(q0 + r) * HD + d4 * 4);
        unsigned* p = qp + r * 68 + d4 * 4;
        p[0] = f2tf(v.x); p[1] = f2tf(v.y); p[2] = f2tf(v.z); p[3] = f2tf(v.w);
    }
    __syncthreads();

    // Q fragments into registers: 8 k-steps x 4 regs
    unsigned aq[8][4];
    {
        const int qr = wid * 16 + g;
#pragma unroll
        for (int ks = 0; ks < 8; ks++) {
            int col = ks * 8 + t4;
            aq[ks][0] = qp[qr * 68 + col];
            aq[ks][1] = qp[(qr + 8) * 68 + col];
            aq[ks][2] = qp[qr * 68 + col + 4];
            aq[ks][3] = qp[(qr + 8) * 68 + col + 4];
        }
    }
    __syncthreads();  // qp now reusable as P

    float m_i[2] = {-1e30f, -1e30f};
    float l_i[2] = {0.f, 0.f};
    float o[8][4];
#pragma unroll
    for (int nt = 0; nt < 8; nt++)
#pragma unroll
        for (int r = 0; r < 4; r++) o[nt][r] = 0.f;

    int c0 = 2 * qt - 2; if (c0 < 0) c0 = 0;
    int c1 = 2 * qt + 3; if (c1 > 31) c1 = 31;

    for (int c = c0; c <= c1; c++) {
        const int j0 = c * 64;
        // stage K, V
#pragma unroll
        for (int i = 0; i < 4; i++) {
            int idx = tid + i * 256;  // 1024: 64 rows x 16 float4
            int r = idx >> 4, d4 = idx & 15;
            float4 kv = *(const float4*)(kg + (size_t)(j0 + r) * HD + d4 * 4);
            unsigned* pk = ksh + r * 68 + d4 * 4;
            pk[0] = f2tf(kv.x); pk[1] = f2tf(kv.y); pk[2] = f2tf(kv.z); pk[3] = f2tf(kv.w);
            float4 vv = *(const float4*)(vg + (size_t)(j0 + r) * HD + d4 * 4);
            unsigned* pv = vsh + r * 68 + d4 * 4;
            pv[0] = f2tf(vv.x); pv[1] = f2tf(vv.y); pv[2] = f2tf(vv.z); pv[3] = f2tf(vv.w);
        }
        __syncthreads();

        // ---- S = Q . K^T ----
        float s[8][4];
#pragma unroll
        for (int nt = 0; nt < 8; nt++)
#pragma unroll
            for (int r = 0; r < 4; r++) s[nt][r] = 0.f;

#pragma unroll
        for (int ks = 0; ks < 8; ks++) {
            const int col = ks * 8 + t4;
#pragma unroll
            for (int nt = 0; nt < 8; nt++) {
                unsigned b[2];
                int key = nt * 8 + g;
                b[0] = ksh[key * 68 + col];
                b[1] = ksh[key * 68 + col + 4];
                mma8(s[nt], aq[ks], b);
            }
        }

        // ---- mask + online softmax (per row half) ----
#pragma unroll
        for (int half = 0; half < 2; half++) {
            const int rowg = q0 + wid * 16 + g + half * 8;
            float mx = -1e30f;
#pragma unroll
            for (int nt = 0; nt < 8; nt++) {
#pragma unroll
                for (int cc = 0; cc < 2; cc++) {
                    int colg = j0 + nt * 8 + t4 * 2 + cc;
                    bool valid = (colg >= rowg - 127) && (colg <= rowg + 128);
                    float v = valid ? s[nt][half * 2 + cc] * SCALE : -1e30f;
                    s[nt][half * 2 + cc] = v;
                    mx = fmaxf(mx, v);
                }
            }
            mx = fmaxf(mx, __shfl_xor_sync(0xffffffffu, mx, 1));
            mx = fmaxf(mx, __shfl_xor_sync(0xffffffffu, mx, 2));
            float mnew = fmaxf(m_i[half], mx);
            float alpha = __expf(m_i[half] - mnew);
            float sum = 0.f;
#pragma unroll
            for (int nt = 0; nt < 8; nt++) {
#pragma unroll
                for (int cc = 0; cc < 2; cc++) {
                    float v = s[nt][half * 2 + cc];
                    float p = (v > -1e29f) ? __expf(v - mnew) : 0.f;
                    sum += p;
                    s[nt][half * 2 + cc] = p;
                }
            }
            sum += __shfl_xor_sync(0xffffffffu, sum, 1);
            sum += __shfl_xor_sync(0xffffffffu, sum, 2);
            l_i[half] = l_i[half] * alpha + sum;
            m_i[half] = mnew;
#pragma unroll
            for (int nt = 0; nt < 8; nt++) {
                o[nt][half * 2] *= alpha;
                o[nt][half * 2 + 1] *= alpha;
            }
            // write P (tf32) to smem
            const int rloc = wid * 16 + g + half * 8;
#pragma unroll
            for (int nt = 0; nt < 8; nt++) {
                qp[rloc * 68 + nt * 8 + t4 * 2]     = f2tf(s[nt][half * 2]);
                qp[rloc * 68 + nt * 8 + t4 * 2 + 1] = f2tf(s[nt][half * 2 + 1]);
            }
        }
        __syncwarp();

        // ---- O += P . V ----
#pragma unroll
        for (int ks = 0; ks < 8; ks++) {
            unsigned ap[4];
            const int rloc = wid * 16 + g;
            const int col = ks * 8 + t4;
            ap[0] = qp[rloc * 68 + col];
            ap[1] = qp[(rloc + 8) * 68 + col];
            ap[2] = qp[rloc * 68 + col + 4];
            ap[3] = qp[(rloc + 8) * 68 + col + 4];
#pragma unroll
            for (int nt = 0; nt < 8; nt++) {
                unsigned b[2];
                int dimc = nt * 8 + g;
                b[0] = vsh[(ks * 8 + t4) * 68 + dimc];
                b[1] = vsh[(ks * 8 + t4 + 4) * 68 + dimc];
                mma8(o[nt], ap, b);
            }
        }
        __syncthreads();
    }

    // ---- epilogue: normalize + write ctx token-major ----
#pragma unroll
    for (int half = 0; half < 2; half++) {
        const int rowg = q0 + wid * 16 + g + half * 8;
        const float invl = 1.f / l_i[half];
        const size_t ob = ((size_t)n * TT + rowg) * DM + h * HD;
#pragma unroll
        for (int nt = 0; nt < 8; nt++) {
            int d = nt * 8 + t4 * 2;
            float2 v = make_float2(o[nt][half * 2] * invl, o[nt][half * 2 + 1] * invl);
            *(float2*)(g_ctx + ob + d) = v;
        }
    }
}

// ---------------------------------------------------------------------------
extern "C" void kernel_launch(void* const* d_in, const int* in_sizes, int n_in,
                              void* d_out, int out_size) {
    const float* x    = (const float*)d_in[0];   // [4,2048,512]
    const float* wqkv = (const float*)d_in[1];   // [1536,512]
    const float* outw = (const float*)d_in[2];   // [512,512]
    const float* outb = (const float*)d_in[3];   // [512]
    float* out = (float*)d_out;

    const int att_smem = (128 * 68 + 2 * 64 * 68) * sizeof(unsigned);  // 69632
    cudaFuncSetAttribute(attn_kernel, cudaFuncAttributeMaxDynamicSharedMemorySize,
                         att_smem);

    gemm_tf32<true><<<dim3(1536 / 64, 8192 / 128), 256>>>(x, wqkv, nullptr, nullptr);
    rope_kernel<<<(NB * NH * TT) / 8, 256>>>();
    attn_kernel<<<dim3(TT / 128, NH, NB), 256, att_smem>>>();
    gemm_tf32<false><<<dim3(512 / 64, 8192 / 128), 256>>>(nullptr, outw, outb, out);
}

// round 3
// speedup vs baseline: 1.5731x; 1.0147x over previous
#include <cuda_runtime.h>
#include <math.h>

#define NB 4
#define TT 2048
#define DM 512
#define NH 8
#define HD 64
#define SCALE 0.125f

// Scratch (no allocation allowed)
__device__ float g_q[NB * NH * TT * HD];
__device__ float g_k[NB * NH * TT * HD];
__device__ float g_v[NB * NH * TT * HD];
__device__ float g_ctx[NB * TT * DM];

// pack two floats -> bf16x2 (e0 in low half), rne
__device__ __forceinline__ unsigned pack2(float e0, float e1) {
    unsigned r;
    asm("cvt.rn.bf16x2.f32 %0, %1, %2;" : "=r"(r) : "f"(e1), "f"(e0));
    return r;
}

// split (f0,f1) into hi bf16x2 + lo (residual) bf16x2
__device__ __forceinline__ void split2(float f0, float f1, unsigned& hi, unsigned& lo) {
    unsigned h = pack2(f0, f1);
    float h0 = __uint_as_float(h << 16);
    float h1 = __uint_as_float(h & 0xFFFF0000u);
    lo = pack2(f0 - h0, f1 - h1);
    hi = h;
}

__device__ __forceinline__ void mmabf(float* c, const unsigned* a, const unsigned* b) {
    asm volatile(
        "mma.sync.aligned.m16n8k16.row.col.f32.bf16.bf16.f32 "
        "{%0,%1,%2,%3},{%4,%5,%6,%7},{%8,%9},{%0,%1,%2,%3};"
        : "+f"(c[0]), "+f"(c[1]), "+f"(c[2]), "+f"(c[3])
        : "r"(a[0]), "r"(a[1]), "r"(a[2]), "r"(a[3]), "r"(b[0]), "r"(b[1]));
}

// ---------------------------------------------------------------------------
// BF16x3 GEMM: C[m][e] = sum_k A[m][k] * W[e][k]
// Block 128m x 64e, 8 warps (4m x 2e), warp tile 32x32. K-chunk 32 (2 k16 steps).
// Double-buffered smem; hi/lo bf16x2 planes, u32 row stride 20 (16 data + 4 pad).
// ---------------------------------------------------------------------------
#define GAH 0
#define GAL 2560
#define GWH 5120
#define GWL 6400
#define GBUF 7680

template <bool QKV>
__global__ void __launch_bounds__(256) gemm_bf(const float* __restrict__ A,
                                               const float* __restrict__ W,
                                               const float* __restrict__ bias,
                                               float* __restrict__ out) {
    extern __shared__ unsigned gsm[];

    const int e0 = blockIdx.x * 64;
    const int m0 = blockIdx.y * 128;
    const int tid = threadIdx.x;
    const int wid = tid >> 5, lane = tid & 31;
    const int wm = wid >> 1, wn = wid & 1;
    const int g = lane >> 2, t4 = lane & 3;

    const float* Ap = QKV ? A : (const float*)g_ctx;

    float acc[2][4][4];
#pragma unroll
    for (int mt = 0; mt < 2; mt++)
#pragma unroll
        for (int nt = 0; nt < 4; nt++)
#pragma unroll
            for (int r = 0; r < 4; r++) acc[mt][nt][r] = 0.f;

    float4 av[4], wv[2];

    // ldg helper (inlined twice)
#define LDG_CHUNK(KC)                                                              \
    do {                                                                           \
        _Pragma("unroll") for (int i = 0; i < 4; i++) {                            \
            int idx = tid + i * 256;                                               \
            int r = idx >> 3, k4 = idx & 7;                                        \
            av[i] = *(const float4*)(Ap + (size_t)(m0 + r) * 512 + (KC) + k4 * 4); \
        }                                                                          \
        _Pragma("unroll") for (int i = 0; i < 2; i++) {                            \
            int idx = tid + i * 256;                                               \
            int r = idx >> 3, k4 = idx & 7;                                        \
            wv[i] = *(const float4*)(W + (size_t)(e0 + r) * 512 + (KC) + k4 * 4);  \
        }                                                                          \
    } while (0)

#define STS_CHUNK(BUF)                                                    \
    do {                                                                  \
        unsigned* b_ = (BUF);                                             \
        _Pragma("unroll") for (int i = 0; i < 4; i++) {                   \
            int idx = tid + i * 256;                                      \
            int r = idx >> 3, k4 = idx & 7;                               \
            unsigned h0, l0, h1, l1;                                      \
            split2(av[i].x, av[i].y, h0, l0);                             \
            split2(av[i].z, av[i].w, h1, l1);                             \
            *(uint2*)&b_[GAH + r * 20 + k4 * 2] = make_uint2(h0, h1);     \
            *(uint2*)&b_[GAL + r * 20 + k4 * 2] = make_uint2(l0, l1);     \
        }                                                                 \
        _Pragma("unroll") for (int i = 0; i < 2; i++) {                   \
            int idx = tid + i * 256;                                      \
            int r = idx >> 3, k4 = idx & 7;                               \
            unsigned h0, l0, h1, l1;                                      \
            split2(wv[i].x, wv[i].y, h0, l0);                             \
            split2(wv[i].z, wv[i].w, h1, l1);                             \
            *(uint2*)&b_[GWH + r * 20 + k4 * 2] = make_uint2(h0, h1);     \
            *(uint2*)&b_[GWL + r * 20 + k4 * 2] = make_uint2(l0, l1);     \
        }                                                                 \
    } while (0)

    LDG_CHUNK(0);
    STS_CHUNK(gsm);
    __syncthreads();

    int cur = 0;
    for (int kc = 0; kc < 512; kc += 32) {
        if (kc + 32 < 512) LDG_CHUNK(kc + 32);
        const unsigned* b = gsm + cur * GBUF;
#pragma unroll
        for (int ks = 0; ks < 2; ks++) {
            const int col = ks * 8 + t4;
            unsigned ah[2][4], al[2][4], bh[4][2], bl[4][2];
#pragma unroll
            for (int mt = 0; mt < 2; mt++) {
                int r = wm * 32 + mt * 16 + g;
                ah[mt][0] = b[GAH + r * 20 + col];
                ah[mt][1] = b[GAH + (r + 8) * 20 + col];
                ah[mt][2] = b[GAH + r * 20 + col + 4];
                ah[mt][3] = b[GAH + (r + 8) * 20 + col + 4];
                al[mt][0] = b[GAL + r * 20 + col];
                al[mt][1] = b[GAL + (r + 8) * 20 + col];
                al[mt][2] = b[GAL + r * 20 + col + 4];
                al[mt][3] = b[GAL + (r + 8) * 20 + col + 4];
            }
#pragma unroll
            for (int nt = 0; nt < 4; nt++) {
                int e = wn * 32 + nt * 8 + g;
                bh[nt][0] = b[GWH + e * 20 + col];
                bh[nt][1] = b[GWH + e * 20 + col + 4];
                bl[nt][0] = b[GWL + e * 20 + col];
                bl[nt][1] = b[GWL + e * 20 + col + 4];
            }
#pragma unroll
            for (int mt = 0; mt < 2; mt++)
#pragma unroll
                for (int nt = 0; nt < 4; nt++) {
                    mmabf(acc[mt][nt], ah[mt], bh[nt]);
                    mmabf(acc[mt][nt], al[mt], bh[nt]);
                    mmabf(acc[mt][nt], ah[mt], bl[nt]);
                }
        }
        if (kc + 32 < 512) STS_CHUNK(gsm + (cur ^ 1) * GBUF);
        __syncthreads();
        cur ^= 1;
    }

    if (QKV) {
        const int sec = e0 >> 9;
        const int h = (e0 >> 6) & 7;
        float* buf = (sec == 0) ? g_q : (sec == 1) ? g_k : g_v;
#pragma unroll
        for (int mt = 0; mt < 2; mt++)
#pragma unroll
            for (int half = 0; half < 2; half++) {
                int m = m0 + wm * 32 + mt * 16 + g + half * 8;
                int nbt = m >> 11, tt = m & 2047;
                size_t base = (((size_t)(nbt * NH + h)) * TT + tt) * HD;
#pragma unroll
                for (int nt = 0; nt < 4; nt++) {
                    int d = wn * 32 + nt * 8 + t4 * 2;
                    *(float2*)(buf + base + d) =
                        make_float2(acc[mt][nt][half * 2], acc[mt][nt][half * 2 + 1]);
                }
            }
    } else {
#pragma unroll
        for (int mt = 0; mt < 2; mt++)
#pragma unroll
            for (int half = 0; half < 2; half++) {
                int m = m0 + wm * 32 + mt * 16 + g + half * 8;
#pragma unroll
                for (int nt = 0; nt < 4; nt++) {
                    int e = e0 + wn * 32 + nt * 8 + t4 * 2;
                    float2 bv = *(const float2*)(bias + e);
                    *(float2*)(out + (size_t)m * 512 + e) =
                        make_float2(acc[mt][nt][half * 2] + bv.x,
                                    acc[mt][nt][half * 2 + 1] + bv.y);
                }
            }
    }
}

// ---------------------------------------------------------------------------
// RoPE in place on g_q and g_k.
// ---------------------------------------------------------------------------
__global__ void __launch_bounds__(256) rope_kernel() {
    int widx = blockIdx.x * 8 + (threadIdx.x >> 5);
    if (widx >= NB * NH * TT) return;
    int lane = threadIdx.x & 31;
    int t = widx & (TT - 1);
    size_t base = (size_t)widx * HD;

    double inv_freq = pow(10000.0, -((double)(2 * lane) / 64.0));
    float ang = (float)t * (float)inv_freq;
    float c = (float)cos((double)ang);
    float s = (float)sin((double)ang);

    float q1 = g_q[base + lane], q2 = g_q[base + lane + 32];
    g_q[base + lane]      = q1 * c - q2 * s;
    g_q[base + lane + 32] = q2 * c + q1 * s;

    float k1 = g_k[base + lane], k2 = g_k[base + lane + 32];
    g_k[base + lane]      = k1 * c - k2 * s;
    g_k[base + lane + 32] = k2 * c + k1 * s;
}

// ---------------------------------------------------------------------------
// Sliding-window attention, bf16x3. Block = 128 q rows x (h, n), 8 warps.
// Key chunks of 128 over {qt-1, qt, qt+1} (middle chunk unmasked by design).
// smem u32 offsets:
#define KHI 0
#define KLO 4608
#define VHI 9216
#define VLO 13568
#define PHI 17920
#define PLO 26624
#define QHI PHI
#define QLO (PHI + 4608)
// ---------------------------------------------------------------------------
__global__ void __launch_bounds__(256) attn_kernel() {
    extern __shared__ unsigned sv[];

    const int qt = blockIdx.x;
    const int h = blockIdx.y;
    const int n = blockIdx.z;
    const int q0 = qt * 128;
    const int tid = threadIdx.x;
    const int wid = tid >> 5, lane = tid & 31;
    const int g = lane >> 2, t4 = lane & 3;
    const int qr = wid * 16 + g;

    const size_t hb = ((size_t)(n * NH + h)) * TT * HD;
    const float* qg = g_q + hb;
    const float* kg = g_k + hb;
    const float* vg = g_v + hb;

    // ---- stage Q (hi/lo planes, stride 36) ----
#pragma unroll
    for (int i = 0; i < 8; i++) {
        int idx = tid + i * 256;
        int r = idx >> 4, d4 = idx & 15;
        float4 v = *(const float4*)(qg + (size_t)(q0 + r) * HD + d4 * 4);
        unsigned h0, l0, h1, l1;
        split2(v.x, v.y, h0, l0);
        split2(v.z, v.w, h1, l1);
        *(uint2*)&sv[QHI + r * 36 + d4 * 2] = make_uint2(h0, h1);
        *(uint2*)&sv[QLO + r * 36 + d4 * 2] = make_uint2(l0, l1);
    }
    __syncthreads();

    // ---- Q fragments: 4 k16-steps ----
    unsigned aqh[4][4], aql[4][4];
#pragma unroll
    for (int ks = 0; ks < 4; ks++) {
        int col = ks * 8 + t4;
        aqh[ks][0] = sv[QHI + qr * 36 + col];
        aqh[ks][1] = sv[QHI + (qr + 8) * 36 + col];
        aqh[ks][2] = sv[QHI + qr * 36 + col + 4];
        aqh[ks][3] = sv[QHI + (qr + 8) * 36 + col + 4];
        aql[ks][0] = sv[QLO + qr * 36 + col];
        aql[ks][1] = sv[QLO + (qr + 8) * 36 + col];
        aql[ks][2] = sv[QLO + qr * 36 + col + 4];
        aql[ks][3] = sv[QLO + (qr + 8) * 36 + col + 4];
    }
    __syncthreads();  // Q area becomes P area

    float m_i[2] = {-1e30f, -1e30f};
    float l_i[2] = {0.f, 0.f};
    float o[8][4];
#pragma unroll
    for (int nt = 0; nt < 8; nt++)
#pragma unroll
        for (int r = 0; r < 4; r++) o[nt][r] = 0.f;

    int c0 = qt - 1; if (c0 < 0) c0 = 0;
    int c1 = qt + 1; if (c1 > 15) c1 = 15;

    for (int c = c0; c <= c1; c++) {
        const int j0 = c * 128;

        // ---- stage K (stride 36) ----
#pragma unroll
        for (int i = 0; i < 8; i++) {
            int idx = tid + i * 256;
            int r = idx >> 4, d4 = idx & 15;
            float4 v = *(const float4*)(kg + (size_t)(j0 + r) * HD + d4 * 4);
            unsigned h0, l0, h1, l1;
            split2(v.x, v.y, h0, l0);
            split2(v.z, v.w, h1, l1);
            *(uint2*)&sv[KHI + r * 36 + d4 * 2] = make_uint2(h0, h1);
            *(uint2*)&sv[KLO + r * 36 + d4 * 2] = make_uint2(l0, l1);
        }
        // ---- stage V transposed: Vt[dim][keypair], stride 68 ----
#pragma unroll
        for (int i = 0; i < 4; i++) {
            int idx = tid + i * 256;
            int rp = idx >> 4, d4 = idx & 15;
            float4 va = *(const float4*)(vg + (size_t)(j0 + 2 * rp) * HD + d4 * 4);
            float4 vb = *(const float4*)(vg + (size_t)(j0 + 2 * rp + 1) * HD + d4 * 4);
            unsigned hh, ll;
            split2(va.x, vb.x, hh, ll);
            sv[VHI + (d4 * 4 + 0) * 68 + rp] = hh; sv[VLO + (d4 * 4 + 0) * 68 + rp] = ll;
            split2(va.y, vb.y, hh, ll);
            sv[VHI + (d4 * 4 + 1) * 68 + rp] = hh; sv[VLO + (d4 * 4 + 1) * 68 + rp] = ll;
            split2(va.z, vb.z, hh, ll);
            sv[VHI + (d4 * 4 + 2) * 68 + rp] = hh; sv[VLO + (d4 * 4 + 2) * 68 + rp] = ll;
            split2(va.w, vb.w, hh, ll);
            sv[VHI + (d4 * 4 + 3) * 68 + rp] = hh; sv[VLO + (d4 * 4 + 3) * 68 + rp] = ll;
        }
        __syncthreads();

        // ---- S = Q . K^T  (16 n-tiles of 8 keys) ----
        float s[16][4];
#pragma unroll
        for (int nt = 0; nt < 16; nt++)
#pragma unroll
            for (int r = 0; r < 4; r++) s[nt][r] = 0.f;

#pragma unroll
        for (int nt = 0; nt < 16; nt++) {
            const unsigned kb = (nt * 8 + g) * 36;
#pragma unroll
            for (int ks = 0; ks < 4; ks++) {
                unsigned bh[2], bl[2];
                bh[0] = sv[KHI + kb + ks * 8 + t4];
                bh[1] = sv[KHI + kb + ks * 8 + t4 + 4];
                bl[0] = sv[KLO + kb + ks * 8 + t4];
                bl[1] = sv[KLO + kb + ks * 8 + t4 + 4];
                mmabf(s[nt], aqh[ks], bh);
                mmabf(s[nt], aql[ks], bh);
                mmabf(s[nt], aqh[ks], bl);
            }
        }

        // ---- mask + online softmax + P split-store ----
#pragma unroll
        for (int half = 0; half < 2; half++) {
            const int rowg = q0 + qr + half * 8;
            float mx = -1e30f;
#pragma unroll
            for (int nt = 0; nt < 16; nt++) {
#pragma unroll
                for (int cc = 0; cc < 2; cc++) {
                    int colg = j0 + nt * 8 + t4 * 2 + cc;
                    bool valid = (colg >= rowg - 127) && (colg <= rowg + 128);
                    float v = valid ? s[nt][half * 2 + cc] * SCALE : -1e30f;
                    s[nt][half * 2 + cc] = v;
                    mx = fmaxf(mx, v);
                }
            }
            mx = fmaxf(mx, __shfl_xor_sync(0xffffffffu, mx, 1));
            mx = fmaxf(mx, __shfl_xor_sync(0xffffffffu, mx, 2));
            float mnew = fmaxf(m_i[half], mx);
            float alpha = __expf(m_i[half] - mnew);
            float sum = 0.f;
#pragma unroll
            for (int nt = 0; nt < 16; nt++) {
#pragma unroll
                for (int cc = 0; cc < 2; cc++) {
                    float v = s[nt][half * 2 + cc];
                    float p = (v > -1e29f) ? __expf(v - mnew) : 0.f;
                    sum += p;
                    s[nt][half * 2 + cc] = p;
                }
            }
            sum += __shfl_xor_sync(0xffffffffu, sum, 1);
            sum += __shfl_xor_sync(0xffffffffu, sum, 2);
            l_i[half] = l_i[half] * alpha + sum;
            m_i[half] = mnew;
#pragma unroll
            for (int nt = 0; nt < 8; nt++) {
                o[nt][half * 2] *= alpha;
                o[nt][half * 2 + 1] *= alpha;
            }
            const int rloc = qr + half * 8;
#pragma unroll
            for (int nt = 0; nt < 16; nt++) {
                unsigned hh, ll;
                split2(s[nt][half * 2], s[nt][half * 2 + 1], hh, ll);
                sv[PHI + rloc * 68 + nt * 4 + t4] = hh;
                sv[PLO + rloc * 68 + nt * 4 + t4] = ll;
            }
        }
        __syncwarp();

        // ---- O += P . V  (8 k16-steps over 128 keys, 8 dim-tiles) ----
#pragma unroll
        for (int ksp = 0; ksp < 8; ksp++) {
            unsigned aph[4], apl[4];
            const int col = ksp * 8 + t4;
            aph[0] = sv[PHI + qr * 68 + col];
            aph[1] = sv[PHI + (qr + 8) * 68 + col];
            aph[2] = sv[PHI + qr * 68 + col + 4];
            aph[3] = sv[PHI + (qr + 8) * 68 + col + 4];
            apl[0] = sv[PLO + qr * 68 + col];
            apl[1] = sv[PLO + (qr + 8) * 68 + col];
            apl[2] = sv[PLO + qr * 68 + col + 4];
            apl[3] = sv[PLO + (qr + 8) * 68 + col + 4];
#pragma unroll
            for (int nt = 0; nt < 8; nt++) {
                const unsigned vb = (nt * 8 + g) * 68 + col;
                unsigned bh[2], bl[2];
                bh[0] = sv[VHI + vb];
                bh[1] = sv[VHI + vb + 4];
                bl[0] = sv[VLO + vb];
                bl[1] = sv[VLO + vb + 4];
                mmabf(o[nt], aph, bh);
                mmabf(o[nt], apl, bh);
                mmabf(o[nt], aph, bl);
            }
        }
        __syncthreads();
    }

    // ---- epilogue ----
#pragma unroll
    for (int half = 0; half < 2; half++) {
        const int rowg = q0 + qr + half * 8;
        const float invl = 1.f / l_i[half];
        const size_t ob = ((size_t)n * TT + rowg) * DM + h * HD;
#pragma unroll
        for (int nt = 0; nt < 8; nt++) {
            int d = nt * 8 + t4 * 2;
            *(float2*)(g_ctx + ob + d) =
                make_float2(o[nt][half * 2] * invl, o[nt][half * 2 + 1] * invl);
        }
    }
}

// ---------------------------------------------------------------------------
extern "C" void kernel_launch(void* const* d_in, const int* in_sizes, int n_in,
                              void* d_out, int out_size) {
    const float* x    = (const float*)d_in[0];   // [4,2048,512]
    const float* wqkv = (const float*)d_in[1];   // [1536,512]
    const float* outw = (const float*)d_in[2];   // [512,512]
    const float* outb = (const float*)d_in[3];   // [512]
    float* out = (float*)d_out;

    const int gemm_smem = 2 * GBUF * sizeof(unsigned);            // 61440
    const int att_smem = (PLO + 128 * 68) * sizeof(unsigned);     // 141312

    cudaFuncSetAttribute(gemm_bf<true>, cudaFuncAttributeMaxDynamicSharedMemorySize, gemm_smem);
    cudaFuncSetAttribute(gemm_bf<false>, cudaFuncAttributeMaxDynamicSharedMemorySize, gemm_smem);
    cudaFuncSetAttribute(attn_kernel, cudaFuncAttributeMaxDynamicSharedMemorySize, att_smem);

    gemm_bf<true><<<dim3(1536 / 64, 8192 / 128), 256, gemm_smem>>>(x, wqkv, nullptr, nullptr);
    rope_kernel<<<(NB * NH * TT) / 8, 256>>>();
    attn_kernel<<<dim3(TT / 128, NH, NB), 256, att_smem>>>();
    gemm_bf<false><<<dim3(512 / 64, 8192 / 128), 256, gemm_smem>>>(nullptr, outw, outb, out);
}

// round 4
// speedup vs baseline: 3.3759x; 2.1460x over previous
#include <cuda_runtime.h>
#include <math.h>

#define NB 4
#define TT 2048
#define DM 512
#define NH 8
#define HD 64
#define SCALE 0.125f

// Scratch (no allocation allowed)
__device__ float g_q[NB * NH * TT * HD];
__device__ float g_k[NB * NH * TT * HD];
__device__ float g_v[NB * NH * TT * HD];
__device__ float g_ctx[NB * TT * DM];
__device__ float g_rc[TT * 32];
__device__ float g_rs[TT * 32];

// pack two floats -> bf16x2 (e0 in low half), rne
__device__ __forceinline__ unsigned pack2(float e0, float e1) {
    unsigned r;
    asm("cvt.rn.bf16x2.f32 %0, %1, %2;" : "=r"(r) : "f"(e1), "f"(e0));
    return r;
}

// split (f0,f1) into hi bf16x2 + lo (residual) bf16x2
__device__ __forceinline__ void split2(float f0, float f1, unsigned& hi, unsigned& lo) {
    unsigned h = pack2(f0, f1);
    float h0 = __uint_as_float(h << 16);
    float h1 = __uint_as_float(h & 0xFFFF0000u);
    lo = pack2(f0 - h0, f1 - h1);
    hi = h;
}

__device__ __forceinline__ void mmabf(float* c, const unsigned* a, const unsigned* b) {
    asm volatile(
        "mma.sync.aligned.m16n8k16.row.col.f32.bf16.bf16.f32 "
        "{%0,%1,%2,%3},{%4,%5,%6,%7},{%8,%9},{%0,%1,%2,%3};"
        : "+f"(c[0]), "+f"(c[1]), "+f"(c[2]), "+f"(c[3])
        : "r"(a[0]), "r"(a[1]), "r"(a[2]), "r"(a[3]), "r"(b[0]), "r"(b[1]));
}

// ---------------------------------------------------------------------------
// BF16x3 GEMM: C[m][e] = sum_k A[m][k] * W[e][k]
// ---------------------------------------------------------------------------
#define GAH 0
#define GAL 2560
#define GWH 5120
#define GWL 6400
#define GBUF 7680

template <bool QKV>
__global__ void __launch_bounds__(256) gemm_bf(const float* __restrict__ A,
                                               const float* __restrict__ W,
                                               const float* __restrict__ bias,
                                               float* __restrict__ out) {
    extern __shared__ unsigned gsm[];

    const int e0 = blockIdx.x * 64;
    const int m0 = blockIdx.y * 128;
    const int tid = threadIdx.x;
    const int wid = tid >> 5, lane = tid & 31;
    const int wm = wid >> 1, wn = wid & 1;
    const int g = lane >> 2, t4 = lane & 3;

    const float* Ap = QKV ? A : (const float*)g_ctx;

    float acc[2][4][4];
#pragma unroll
    for (int mt = 0; mt < 2; mt++)
#pragma unroll
        for (int nt = 0; nt < 4; nt++)
#pragma unroll
            for (int r = 0; r < 4; r++) acc[mt][nt][r] = 0.f;

    float4 av[4], wv[2];

#define LDG_CHUNK(KC)                                                              \
    do {                                                                           \
        _Pragma("unroll") for (int i = 0; i < 4; i++) {                            \
            int idx = tid + i * 256;                                               \
            int r = idx >> 3, k4 = idx & 7;                                        \
            av[i] = *(const float4*)(Ap + (size_t)(m0 + r) * 512 + (KC) + k4 * 4); \
        }                                                                          \
        _Pragma("unroll") for (int i = 0; i < 2; i++) {                            \
            int idx = tid + i * 256;                                               \
            int r = idx >> 3, k4 = idx & 7;                                        \
            wv[i] = *(const float4*)(W + (size_t)(e0 + r) * 512 + (KC) + k4 * 4);  \
        }                                                                          \
    } while (0)

#define STS_CHUNK(BUF)                                                    \
    do {                                                                  \
        unsigned* b_ = (BUF);                                             \
        _Pragma("unroll") for (int i = 0; i < 4; i++) {                   \
            int idx = tid + i * 256;                                      \
            int r = idx >> 3, k4 = idx & 7;                               \
            unsigned h0, l0, h1, l1;                                      \
            split2(av[i].x, av[i].y, h0, l0);                             \
            split2(av[i].z, av[i].w, h1, l1);                             \
            *(uint2*)&b_[GAH + r * 20 + k4 * 2] = make_uint2(h0, h1);     \
            *(uint2*)&b_[GAL + r * 20 + k4 * 2] = make_uint2(l0, l1);     \
        }                                                                 \
        _Pragma("unroll") for (int i = 0; i < 2; i++) {                   \
            int idx = tid + i * 256;                                      \
            int r = idx >> 3, k4 = idx & 7;                               \
            unsigned h0, l0, h1, l1;                                      \
            split2(wv[i].x, wv[i].y, h0, l0);                             \
            split2(wv[i].z, wv[i].w, h1, l1);                             \
            *(uint2*)&b_[GWH + r * 20 + k4 * 2] = make_uint2(h0, h1);     \
            *(uint2*)&b_[GWL + r * 20 + k4 * 2] = make_uint2(l0, l1);     \
        }                                                                 \
    } while (0)

    LDG_CHUNK(0);
    STS_CHUNK(gsm);
    __syncthreads();

    int cur = 0;
    for (int kc = 0; kc < 512; kc += 32) {
        if (kc + 32 < 512) LDG_CHUNK(kc + 32);
        const unsigned* b = gsm + cur * GBUF;
#pragma unroll
        for (int ks = 0; ks < 2; ks++) {
            const int col = ks * 8 + t4;
            unsigned ah[2][4], al[2][4], bh[4][2], bl[4][2];
#pragma unroll
            for (int mt = 0; mt < 2; mt++) {
                int r = wm * 32 + mt * 16 + g;
                ah[mt][0] = b[GAH + r * 20 + col];
                ah[mt][1] = b[GAH + (r + 8) * 20 + col];
                ah[mt][2] = b[GAH + r * 20 + col + 4];
                ah[mt][3] = b[GAH + (r + 8) * 20 + col + 4];
                al[mt][0] = b[GAL + r * 20 + col];
                al[mt][1] = b[GAL + (r + 8) * 20 + col];
                al[mt][2] = b[GAL + r * 20 + col + 4];
                al[mt][3] = b[GAL + (r + 8) * 20 + col + 4];
            }
#pragma unroll
            for (int nt = 0; nt < 4; nt++) {
                int e = wn * 32 + nt * 8 + g;
                bh[nt][0] = b[GWH + e * 20 + col];
                bh[nt][1] = b[GWH + e * 20 + col + 4];
                bl[nt][0] = b[GWL + e * 20 + col];
                bl[nt][1] = b[GWL + e * 20 + col + 4];
            }
#pragma unroll
            for (int mt = 0; mt < 2; mt++)
#pragma unroll
                for (int nt = 0; nt < 4; nt++) {
                    mmabf(acc[mt][nt], ah[mt], bh[nt]);
                    mmabf(acc[mt][nt], al[mt], bh[nt]);
                    mmabf(acc[mt][nt], ah[mt], bl[nt]);
                }
        }
        if (kc + 32 < 512) STS_CHUNK(gsm + (cur ^ 1) * GBUF);
        __syncthreads();
        cur ^= 1;
    }

    if (QKV) {
        const int sec = e0 >> 9;
        const int h = (e0 >> 6) & 7;
        float* buf = (sec == 0) ? g_q : (sec == 1) ? g_k : g_v;
#pragma unroll
        for (int mt = 0; mt < 2; mt++)
#pragma unroll
            for (int half = 0; half < 2; half++) {
                int m = m0 + wm * 32 + mt * 16 + g + half * 8;
                int nbt = m >> 11, tt = m & 2047;
                size_t base = (((size_t)(nbt * NH + h)) * TT + tt) * HD;
#pragma unroll
                for (int nt = 0; nt < 4; nt++) {
                    int d = wn * 32 + nt * 8 + t4 * 2;
                    *(float2*)(buf + base + d) =
                        make_float2(acc[mt][nt][half * 2], acc[mt][nt][half * 2 + 1]);
                }
            }
    } else {
#pragma unroll
        for (int mt = 0; mt < 2; mt++)
#pragma unroll
            for (int half = 0; half < 2; half++) {
                int m = m0 + wm * 32 + mt * 16 + g + half * 8;
#pragma unroll
                for (int nt = 0; nt < 4; nt++) {
                    int e = e0 + wn * 32 + nt * 8 + t4 * 2;
                    float2 bv = *(const float2*)(bias + e);
                    *(float2*)(out + (size_t)m * 512 + e) =
                        make_float2(acc[mt][nt][half * 2] + bv.x,
                                    acc[mt][nt][half * 2 + 1] + bv.y);
                }
            }
    }
}

// ---------------------------------------------------------------------------
// RoPE trig table: one thread per (t, pair). 65536 threads total.
// Same math as before (double pow/cos/sin of the fp32 angle) -> identical values.
// ---------------------------------------------------------------------------
__global__ void __launch_bounds__(256) rope_table_kernel() {
    int idx = blockIdx.x * 256 + threadIdx.x;
    if (idx >= TT * 32) return;
    int t = idx >> 5, lane = idx & 31;
    double inv_freq = pow(10000.0, -((double)(2 * lane) / 64.0));
    float ang = (float)t * (float)inv_freq;
    g_rc[idx] = (float)cos((double)ang);
    g_rs[idx] = (float)sin((double)ang);
}

// ---------------------------------------------------------------------------
// RoPE in place on g_q and g_k, reading the table. One warp per (n,h,t) row.
// ---------------------------------------------------------------------------
__global__ void __launch_bounds__(256) rope_kernel() {
    int widx = blockIdx.x * 8 + (threadIdx.x >> 5);
    if (widx >= NB * NH * TT) return;
    int lane = threadIdx.x & 31;
    int t = widx & (TT - 1);
    size_t base = (size_t)widx * HD;

    float c = g_rc[t * 32 + lane];
    float s = g_rs[t * 32 + lane];

    float q1 = g_q[base + lane], q2 = g_q[base + lane + 32];
    g_q[base + lane]      = q1 * c - q2 * s;
    g_q[base + lane + 32] = q2 * c + q1 * s;

    float k1 = g_k[base + lane], k2 = g_k[base + lane + 32];
    g_k[base + lane]      = k1 * c - k2 * s;
    g_k[base + lane + 32] = k2 * c + k1 * s;
}

// ---------------------------------------------------------------------------
// Sliding-window attention, bf16x3, with per-warp tile-range skipping.
// ---------------------------------------------------------------------------
#define KHI 0
#define KLO 4608
#define VHI 9216
#define VLO 13568
#define PHI 17920
#define PLO 26624
#define QHI PHI
#define QLO (PHI + 4608)

__global__ void __launch_bounds__(256) attn_kernel() {
    extern __shared__ unsigned sv[];

    const int qt = blockIdx.x;
    const int h = blockIdx.y;
    const int n = blockIdx.z;
    const int q0 = qt * 128;
    const int tid = threadIdx.x;
    const int wid = tid >> 5, lane = tid & 31;
    const int g = lane >> 2, t4 = lane & 3;
    const int qr = wid * 16 + g;

    const size_t hb = ((size_t)(n * NH + h)) * TT * HD;
    const float* qg = g_q + hb;
    const float* kg = g_k + hb;
    const float* vg = g_v + hb;

    // ---- stage Q (hi/lo planes, stride 36) ----
#pragma unroll
    for (int i = 0; i < 8; i++) {
        int idx = tid + i * 256;
        int r = idx >> 4, d4 = idx & 15;
        float4 v = *(const float4*)(qg + (size_t)(q0 + r) * HD + d4 * 4);
        unsigned h0, l0, h1, l1;
        split2(v.x, v.y, h0, l0);
        split2(v.z, v.w, h1, l1);
        *(uint2*)&sv[QHI + r * 36 + d4 * 2] = make_uint2(h0, h1);
        *(uint2*)&sv[QLO + r * 36 + d4 * 2] = make_uint2(l0, l1);
    }
    __syncthreads();

    unsigned aqh[4][4], aql[4][4];
#pragma unroll
    for (int ks = 0; ks < 4; ks++) {
        int col = ks * 8 + t4;
        aqh[ks][0] = sv[QHI + qr * 36 + col];
        aqh[ks][1] = sv[QHI + (qr + 8) * 36 + col];
        aqh[ks][2] = sv[QHI + qr * 36 + col + 4];
        aqh[ks][3] = sv[QHI + (qr + 8) * 36 + col + 4];
        aql[ks][0] = sv[QLO + qr * 36 + col];
        aql[ks][1] = sv[QLO + (qr + 8) * 36 + col];
        aql[ks][2] = sv[QLO + qr * 36 + col + 4];
        aql[ks][3] = sv[QLO + (qr + 8) * 36 + col + 4];
    }
    __syncthreads();

    float m_i[2] = {-1e30f, -1e30f};
    float l_i[2] = {0.f, 0.f};
    float o[8][4];
#pragma unroll
    for (int nt = 0; nt < 8; nt++)
#pragma unroll
        for (int r = 0; r < 4; r++) o[nt][r] = 0.f;

    int c0 = qt - 1; if (c0 < 0) c0 = 0;
    int c1 = qt + 1; if (c1 > 15) c1 = 15;

    for (int c = c0; c <= c1; c++) {
        const int j0 = c * 128;

        // valid n-tile range for this warp (even/odd aligned to PV k16 steps)
        const int rowlo = q0 + wid * 16;
        int ntLo = (rowlo - 127 - j0) >> 3;
        if (ntLo < 0) ntLo = 0;
        ntLo &= ~1;
        int ntHi = (rowlo + 15 + 128 - j0) >> 3;
        if (ntHi > 15) ntHi = 15;
        ntHi |= 1;
        const int kspLo = ntLo >> 1, kspHi = ntHi >> 1;

        // ---- stage K ----
#pragma unroll
        for (int i = 0; i < 8; i++) {
            int idx = tid + i * 256;
            int r = idx >> 4, d4 = idx & 15;
            float4 v = *(const float4*)(kg + (size_t)(j0 + r) * HD + d4 * 4);
            unsigned h0, l0, h1, l1;
            split2(v.x, v.y, h0, l0);
            split2(v.z, v.w, h1, l1);
            *(uint2*)&sv[KHI + r * 36 + d4 * 2] = make_uint2(h0, h1);
            *(uint2*)&sv[KLO + r * 36 + d4 * 2] = make_uint2(l0, l1);
        }
        // ---- stage V transposed ----
#pragma unroll
        for (int i = 0; i < 4; i++) {
            int idx = tid + i * 256;
            int rp = idx >> 4, d4 = idx & 15;
            float4 va = *(const float4*)(vg + (size_t)(j0 + 2 * rp) * HD + d4 * 4);
            float4 vb = *(const float4*)(vg + (size_t)(j0 + 2 * rp + 1) * HD + d4 * 4);
            unsigned hh, ll;
            split2(va.x, vb.x, hh, ll);
            sv[VHI + (d4 * 4 + 0) * 68 + rp] = hh; sv[VLO + (d4 * 4 + 0) * 68 + rp] = ll;
            split2(va.y, vb.y, hh, ll);
            sv[VHI + (d4 * 4 + 1) * 68 + rp] = hh; sv[VLO + (d4 * 4 + 1) * 68 + rp] = ll;
            split2(va.z, vb.z, hh, ll);
            sv[VHI + (d4 * 4 + 2) * 68 + rp] = hh; sv[VLO + (d4 * 4 + 2) * 68 + rp] = ll;
            split2(va.w, vb.w, hh, ll);
            sv[VHI + (d4 * 4 + 3) * 68 + rp] = hh; sv[VLO + (d4 * 4 + 3) * 68 + rp] = ll;
        }
        __syncthreads();

        // ---- S = Q . K^T (only live n-tiles) ----
        float s[16][4];
#pragma unroll
        for (int nt = 0; nt < 16; nt++)
#pragma unroll
            for (int r = 0; r < 4; r++) s[nt][r] = 0.f;

#pragma unroll
        for (int nt = 0; nt < 16; nt++) {
            if (nt < ntLo || nt > ntHi) continue;
            const unsigned kb = (nt * 8 + g) * 36;
#pragma unroll
            for (int ks = 0; ks < 4; ks++) {
                unsigned bh[2], bl[2];
                bh[0] = sv[KHI + kb + ks * 8 + t4];
                bh[1] = sv[KHI + kb + ks * 8 + t4 + 4];
                bl[0] = sv[KLO + kb + ks * 8 + t4];
                bl[1] = sv[KLO + kb + ks * 8 + t4 + 4];
                mmabf(s[nt], aqh[ks], bh);
                mmabf(s[nt], aql[ks], bh);
                mmabf(s[nt], aqh[ks], bl);
            }
        }

        // ---- mask + online softmax + P split-store ----
#pragma unroll
        for (int half = 0; half < 2; half++) {
            const int rowg = q0 + qr + half * 8;
            float mx = -1e30f;
#pragma unroll
            for (int nt = 0; nt < 16; nt++) {
                if (nt < ntLo || nt > ntHi) continue;
#pragma unroll
                for (int cc = 0; cc < 2; cc++) {
                    int colg = j0 + nt * 8 + t4 * 2 + cc;
                    bool valid = (colg >= rowg - 127) && (colg <= rowg + 128);
                    float v = valid ? s[nt][half * 2 + cc] * SCALE : -1e30f;
                    s[nt][half * 2 + cc] = v;
                    mx = fmaxf(mx, v);
                }
            }
            mx = fmaxf(mx, __shfl_xor_sync(0xffffffffu, mx, 1));
            mx = fmaxf(mx, __shfl_xor_sync(0xffffffffu, mx, 2));
            float mnew = fmaxf(m_i[half], mx);
            float alpha = __expf(m_i[half] - mnew);
            float sum = 0.f;
#pragma unroll
            for (int nt = 0; nt < 16; nt++) {
                if (nt < ntLo || nt > ntHi) continue;
#pragma unroll
                for (int cc = 0; cc < 2; cc++) {
                    float v = s[nt][half * 2 + cc];
                    float p = (v > -1e29f) ? __expf(v - mnew) : 0.f;
                    sum += p;
                    s[nt][half * 2 + cc] = p;
                }
            }
            sum += __shfl_xor_sync(0xffffffffu, sum, 1);
            sum += __shfl_xor_sync(0xffffffffu, sum, 2);
            l_i[half] = l_i[half] * alpha + sum;
            m_i[half] = mnew;
#pragma unroll
            for (int nt = 0; nt < 8; nt++) {
                o[nt][half * 2] *= alpha;
                o[nt][half * 2 + 1] *= alpha;
            }
            const int rloc = qr + half * 8;
#pragma unroll
            for (int nt = 0; nt < 16; nt++) {
                if (nt < ntLo || nt > ntHi) continue;
                unsigned hh, ll;
                split2(s[nt][half * 2], s[nt][half * 2 + 1], hh, ll);
                sv[PHI + rloc * 68 + nt * 4 + t4] = hh;
                sv[PLO + rloc * 68 + nt * 4 + t4] = ll;
            }
        }
        __syncwarp();

        // ---- O += P . V (only live k-steps) ----
#pragma unroll
        for (int ksp = 0; ksp < 8; ksp++) {
            if (ksp < kspLo || ksp > kspHi) continue;
            unsigned aph[4], apl[4];
            const int col = ksp * 8 + t4;
            aph[0] = sv[PHI + qr * 68 + col];
            aph[1] = sv[PHI + (qr + 8) * 68 + col];
            aph[2] = sv[PHI + qr * 68 + col + 4];
            aph[3] = sv[PHI + (qr + 8) * 68 + col + 4];
            apl[0] = sv[PLO + qr * 68 + col];
            apl[1] = sv[PLO + (qr + 8) * 68 + col];
            apl[2] = sv[PLO + qr * 68 + col + 4];
            apl[3] = sv[PLO + (qr + 8) * 68 + col + 4];
#pragma unroll
            for (int nt = 0; nt < 8; nt++) {
                const unsigned vb = (nt * 8 + g) * 68 + col;
                unsigned bh[2], bl[2];
                bh[0] = sv[VHI + vb];
                bh[1] = sv[VHI + vb + 4];
                bl[0] = sv[VLO + vb];
                bl[1] = sv[VLO + vb + 4];
                mmabf(o[nt], aph, bh);
                mmabf(o[nt], apl, bh);
                mmabf(o[nt], aph, bl);
            }
        }
        __syncthreads();
    }

    // ---- epilogue ----
#pragma unroll
    for (int half = 0; half < 2; half++) {
        const int rowg = q0 + qr + half * 8;
        const float invl = 1.f / l_i[half];
        const size_t ob = ((size_t)n * TT + rowg) * DM + h * HD;
#pragma unroll
        for (int nt = 0; nt < 8; nt++) {
            int d = nt * 8 + t4 * 2;
            *(float2*)(g_ctx + ob + d) =
                make_float2(o[nt][half * 2] * invl, o[nt][half * 2 + 1] * invl);
        }
    }
}

// ---------------------------------------------------------------------------
extern "C" void kernel_launch(void* const* d_in, const int* in_sizes, int n_in,
                              void* d_out, int out_size) {
    const float* x    = (const float*)d_in[0];   // [4,2048,512]
    const float* wqkv = (const float*)d_in[1];   // [1536,512]
    const float* outw = (const float*)d_in[2];   // [512,512]
    const float* outb = (const float*)d_in[3];   // [512]
    float* out = (float*)d_out;

    const int gemm_smem = 2 * GBUF * sizeof(unsigned);            // 61440
    const int att_smem = (PLO + 128 * 68) * sizeof(unsigned);     // 141312

    cudaFuncSetAttribute(gemm_bf<true>, cudaFuncAttributeMaxDynamicSharedMemorySize, gemm_smem);
    cudaFuncSetAttribute(gemm_bf<false>, cudaFuncAttributeMaxDynamicSharedMemorySize, gemm_smem);
    cudaFuncSetAttribute(attn_kernel, cudaFuncAttributeMaxDynamicSharedMemorySize, att_smem);

    rope_table_kernel<<<(TT * 32 + 255) / 256, 256>>>();
    gemm_bf<true><<<dim3(1536 / 64, 8192 / 128), 256, gemm_smem>>>(x, wqkv, nullptr, nullptr);
    rope_kernel<<<(NB * NH * TT) / 8, 256>>>();
    attn_kernel<<<dim3(TT / 128, NH, NB), 256, att_smem>>>();
    gemm_bf<false><<<dim3(512 / 64, 8192 / 128), 256, gemm_smem>>>(nullptr, outw, outb, out);
}

// round 6
// speedup vs baseline: 3.8295x; 1.1343x over previous
#include <cuda_runtime.h>
#include <math.h>
#include <cstdint>

#define NB 4
#define TT 2048
#define DM 512
#define NH 8
#define HD 64
#define SCALE 0.125f

// Scratch (no allocation allowed)
__device__ float g_q[NB * NH * TT * HD];
__device__ float g_k[NB * NH * TT * HD];
__device__ float g_v[NB * NH * TT * HD];
__device__ float g_ctx[NB * TT * DM];
__device__ float g_rc[TT * 32];
__device__ float g_rs[TT * 32];

// pack two floats -> bf16x2 (e0 in low half), rne
__device__ __forceinline__ unsigned pack2(float e0, float e1) {
    unsigned r;
    asm("cvt.rn.bf16x2.f32 %0, %1, %2;" : "=r"(r) : "f"(e1), "f"(e0));
    return r;
}
__device__ __forceinline__ void split2(float f0, float f1, unsigned& hi, unsigned& lo) {
    unsigned h = pack2(f0, f1);
    float h0 = __uint_as_float(h << 16);
    float h1 = __uint_as_float(h & 0xFFFF0000u);
    lo = pack2(f0 - h0, f1 - h1);
    hi = h;
}
__device__ __forceinline__ void mmabf(float* c, const unsigned* a, const unsigned* b) {
    asm volatile(
        "mma.sync.aligned.m16n8k16.row.col.f32.bf16.bf16.f32 "
        "{%0,%1,%2,%3},{%4,%5,%6,%7},{%8,%9},{%0,%1,%2,%3};"
        : "+f"(c[0]), "+f"(c[1]), "+f"(c[2]), "+f"(c[3])
        : "r"(a[0]), "r"(a[1]), "r"(a[2]), "r"(a[3]), "r"(b[0]), "r"(b[1]));
}
__device__ __forceinline__ uint32_t smem_u32(const void* p) {
    uint32_t a;
    asm("{ .reg .u64 t; cvta.to.shared.u64 t, %1; cvt.u32.u64 %0, t; }" : "=r"(a) : "l"(p));
    return a;
}
__device__ __forceinline__ void ldsm_x4(unsigned* r, uint32_t addr) {
    asm volatile("ldmatrix.sync.aligned.m8n8.x4.shared.b16 {%0,%1,%2,%3}, [%4];"
                 : "=r"(r[0]), "=r"(r[1]), "=r"(r[2]), "=r"(r[3]) : "r"(addr));
}

// ---------------------------------------------------------------------------
// BF16x3 GEMM with ldmatrix fragment loads.
// Block 128m x 64e, 8 warps (4m x 2e), warp tile 32x32, K-chunk 32, dbl-buffered.
// smem u32 row stride 20 (80B = 5*16B: ldmatrix-aligned, conflict-free).
// ---------------------------------------------------------------------------
#define GAH 0
#define GAL 2560
#define GWH 5120
#define GWL 6400
#define GBUF 7680

template <bool QKV>
__global__ void __launch_bounds__(256) gemm_bf(const float* __restrict__ A,
                                               const float* __restrict__ W,
                                               const float* __restrict__ bias,
                                               float* __restrict__ out) {
    extern __shared__ unsigned gsm[];
    const uint32_t sbase = smem_u32(gsm);

    const int e0 = blockIdx.x * 64;
    const int m0 = blockIdx.y * 128;
    const int tid = threadIdx.x;
    const int wid = tid >> 5, lane = tid & 31;
    const int wm = wid >> 1, wn = wid & 1;
    const int g = lane >> 2, t4 = lane & 3;

    const float* Ap = QKV ? A : (const float*)g_ctx;

    float acc[2][4][4];
#pragma unroll
    for (int mt = 0; mt < 2; mt++)
#pragma unroll
        for (int nt = 0; nt < 4; nt++)
#pragma unroll
            for (int r = 0; r < 4; r++) acc[mt][nt][r] = 0.f;

    float4 av[4], wv[2];

#define LDG_CHUNK(KC)                                                              \
    do {                                                                           \
        _Pragma("unroll") for (int i = 0; i < 4; i++) {                            \
            int idx = tid + i * 256;                                               \
            int r = idx >> 3, k4 = idx & 7;                                        \
            av[i] = *(const float4*)(Ap + (size_t)(m0 + r) * 512 + (KC) + k4 * 4); \
        }                                                                          \
        _Pragma("unroll") for (int i = 0; i < 2; i++) {                            \
            int idx = tid + i * 256;                                               \
            int r = idx >> 3, k4 = idx & 7;                                        \
            wv[i] = *(const float4*)(W + (size_t)(e0 + r) * 512 + (KC) + k4 * 4);  \
        }                                                                          \
    } while (0)

#define STS_CHUNK(BUF)                                                    \
    do {                                                                  \
        unsigned* b_ = (BUF);                                             \
        _Pragma("unroll") for (int i = 0; i < 4; i++) {                   \
            int idx = tid + i * 256;                                      \
            int r = idx >> 3, k4 = idx & 7;                               \
            unsigned h0, l0, h1, l1;                                      \
            split2(av[i].x, av[i].y, h0, l0);                             \
            split2(av[i].z, av[i].w, h1, l1);                             \
            *(uint2*)&b_[GAH + r * 20 + k4 * 2] = make_uint2(h0, h1);     \
            *(uint2*)&b_[GAL + r * 20 + k4 * 2] = make_uint2(l0, l1);     \
        }                                                                 \
        _Pragma("unroll") for (int i = 0; i < 2; i++) {                   \
            int idx = tid + i * 256;                                      \
            int r = idx >> 3, k4 = idx & 7;                               \
            unsigned h0, l0, h1, l1;                                      \
            split2(wv[i].x, wv[i].y, h0, l0);                             \
            split2(wv[i].z, wv[i].w, h1, l1);                             \
            *(uint2*)&b_[GWH + r * 20 + k4 * 2] = make_uint2(h0, h1);     \
            *(uint2*)&b_[GWL + r * 20 + k4 * 2] = make_uint2(l0, l1);     \
        }                                                                 \
    } while (0)

    LDG_CHUNK(0);
    STS_CHUNK(gsm);
    __syncthreads();

    // ldmatrix lane-address components (bytes)
    const uint32_t aRowOff = (uint32_t)(lane & 15) * 80;          // A/B row stride 80B
    const uint32_t aColOff = (uint32_t)(lane >> 4) * 16;          // k-half
    const uint32_t bRowOff = (uint32_t)((lane & 7) + ((lane >> 4) << 3)) * 80;
    const uint32_t bColOff = (uint32_t)((lane >> 3) & 1) * 16;

    int cur = 0;
    for (int kc = 0; kc < 512; kc += 32) {
        if (kc + 32 < 512) LDG_CHUNK(kc + 32);
        const uint32_t bb = sbase + cur * (GBUF * 4);
#pragma unroll
        for (int ks = 0; ks < 2; ks++) {
            unsigned ah[2][4], al[2][4], bh[2][4], bl[2][4];
            const uint32_t kOff = ks * 32;  // 8 u32 = 32B
#pragma unroll
            for (int mt = 0; mt < 2; mt++) {
                uint32_t base = bb + (wm * 32 + mt * 16) * 80 + aRowOff + kOff + aColOff;
                ldsm_x4(ah[mt], base + GAH * 4);
                ldsm_x4(al[mt], base + GAL * 4);
            }
#pragma unroll
            for (int ntp = 0; ntp < 2; ntp++) {
                uint32_t base = bb + (wn * 32 + ntp * 16) * 80 + bRowOff + kOff + bColOff;
                ldsm_x4(bh[ntp], base + GWH * 4);
                ldsm_x4(bl[ntp], base + GWL * 4);
            }
#pragma unroll
            for (int mt = 0; mt < 2; mt++)
#pragma unroll
                for (int nt = 0; nt < 4; nt++) {
                    const unsigned* BH = &bh[nt >> 1][(nt & 1) * 2];
                    const unsigned* BL = &bl[nt >> 1][(nt & 1) * 2];
                    mmabf(acc[mt][nt], ah[mt], BH);
                    mmabf(acc[mt][nt], al[mt], BH);
                    mmabf(acc[mt][nt], ah[mt], BL);
                }
        }
        if (kc + 32 < 512) STS_CHUNK(gsm + (cur ^ 1) * GBUF);
        __syncthreads();
        cur ^= 1;
    }

    if (QKV) {
        const int sec = e0 >> 9;
        const int h = (e0 >> 6) & 7;
        float* buf = (sec == 0) ? g_q : (sec == 1) ? g_k : g_v;
#pragma unroll
        for (int mt = 0; mt < 2; mt++)
#pragma unroll
            for (int half = 0; half < 2; half++) {
                int m = m0 + wm * 32 + mt * 16 + g + half * 8;
                int nbt = m >> 11, tt = m & 2047;
                size_t base = (((size_t)(nbt * NH + h)) * TT + tt) * HD;
#pragma unroll
                for (int nt = 0; nt < 4; nt++) {
                    int d = wn * 32 + nt * 8 + t4 * 2;
                    *(float2*)(buf + base + d) =
                        make_float2(acc[mt][nt][half * 2], acc[mt][nt][half * 2 + 1]);
                }
            }
    } else {
#pragma unroll
        for (int mt = 0; mt < 2; mt++)
#pragma unroll
            for (int half = 0; half < 2; half++) {
                int m = m0 + wm * 32 + mt * 16 + g + half * 8;
#pragma unroll
                for (int nt = 0; nt < 4; nt++) {
                    int e = e0 + wn * 32 + nt * 8 + t4 * 2;
                    float2 bv = *(const float2*)(bias + e);
                    *(float2*)(out + (size_t)m * 512 + e) =
                        make_float2(acc[mt][nt][half * 2] + bv.x,
                                    acc[mt][nt][half * 2 + 1] + bv.y);
                }
            }
    }
}

// ---------------------------------------------------------------------------
// RoPE trig table (double math once; applied inside attention staging)
// ---------------------------------------------------------------------------
__global__ void __launch_bounds__(256) rope_table_kernel() {
    int idx = blockIdx.x * 256 + threadIdx.x;
    if (idx >= TT * 32) return;
    int t = idx >> 5, lane = idx & 31;
    double inv_freq = pow(10000.0, -((double)(2 * lane) / 64.0));
    float ang = (float)t * (float)inv_freq;
    g_rc[idx] = (float)cos((double)ang);
    g_rs[idx] = (float)sin((double)ang);
}

// ---------------------------------------------------------------------------
// Sliding-window attention, bf16x3, ldmatrix fragments, RoPE fused in staging.
// ---------------------------------------------------------------------------
#define KHI 0
#define KLO 4608
#define VHI 9216
#define VLO 13568
#define PHI 17920
#define PLO 26624
#define QHI PHI
#define QLO (PHI + 4608)

__global__ void __launch_bounds__(256) attn_kernel() {
    extern __shared__ unsigned sv[];
    const uint32_t sbase = smem_u32(sv);

    const int qt = blockIdx.x;
    const int h = blockIdx.y;
    const int n = blockIdx.z;
    const int q0 = qt * 128;
    const int tid = threadIdx.x;
    const int wid = tid >> 5, lane = tid & 31;
    const int g = lane >> 2, t4 = lane & 3;
    const int qr = wid * 16 + g;

    const size_t hb = ((size_t)(n * NH + h)) * TT * HD;
    const float* qg = g_q + hb;
    const float* kg = g_k + hb;
    const float* vg = g_v + hb;

    // ldmatrix lane-address components (bytes)
    const uint32_t aRow36 = (uint32_t)(lane & 15) * 144;   // stride 36 u32
    const uint32_t aRow68 = (uint32_t)(lane & 15) * 272;   // stride 68 u32
    const uint32_t aColH = (uint32_t)(lane >> 4) * 16;
    const uint32_t bRow36 = (uint32_t)((lane & 7) + ((lane >> 4) << 3)) * 144;
    const uint32_t bRow68 = (uint32_t)((lane & 7) + ((lane >> 4) << 3)) * 272;
    const uint32_t bColH = (uint32_t)((lane >> 3) & 1) * 16;

    // ---- stage Q with fused RoPE (hi/lo planes, stride 36) ----
#pragma unroll
    for (int i = 0; i < 4; i++) {
        int idx = tid + i * 256;           // 1024: 128 rows x 8 d4 (lower half dims)
        int r = idx >> 3, d4 = idx & 7;
        const float* row = qg + (size_t)(q0 + r) * HD;
        float4 a = *(const float4*)(row + d4 * 4);
        float4 b = *(const float4*)(row + d4 * 4 + 32);
        const float4 cv = *(const float4*)(g_rc + (size_t)(q0 + r) * 32 + d4 * 4);
        const float4 sn = *(const float4*)(g_rs + (size_t)(q0 + r) * 32 + d4 * 4);
        float4 lo = make_float4(a.x * cv.x - b.x * sn.x, a.y * cv.y - b.y * sn.y,
                                a.z * cv.z - b.z * sn.z, a.w * cv.w - b.w * sn.w);
        float4 hi = make_float4(b.x * cv.x + a.x * sn.x, b.y * cv.y + a.y * sn.y,
                                b.z * cv.z + a.z * sn.z, b.w * cv.w + a.w * sn.w);
        unsigned h0, l0, h1, l1;
        split2(lo.x, lo.y, h0, l0);
        split2(lo.z, lo.w, h1, l1);
        *(uint2*)&sv[QHI + r * 36 + d4 * 2] = make_uint2(h0, h1);
        *(uint2*)&sv[QLO + r * 36 + d4 * 2] = make_uint2(l0, l1);
        split2(hi.x, hi.y, h0, l0);
        split2(hi.z, hi.w, h1, l1);
        *(uint2*)&sv[QHI + r * 36 + (d4 + 8) * 2] = make_uint2(h0, h1);
        *(uint2*)&sv[QLO + r * 36 + (d4 + 8) * 2] = make_uint2(l0, l1);
    }
    __syncthreads();

    unsigned aqh[4][4], aql[4][4];
#pragma unroll
    for (int ks = 0; ks < 4; ks++) {
        uint32_t base = sbase + qr / 16 * 0 + (wid * 16) * 144 + aRow36 + ks * 32 + aColH;
        ldsm_x4(aqh[ks], base + QHI * 4);
        ldsm_x4(aql[ks], base + QLO * 4);
    }
    __syncthreads();

    float m_i[2] = {-1e30f, -1e30f};
    float l_i[2] = {0.f, 0.f};
    float o[8][4];
#pragma unroll
    for (int nt = 0; nt < 8; nt++)
#pragma unroll
        for (int r = 0; r < 4; r++) o[nt][r] = 0.f;

    int c0 = qt - 1; if (c0 < 0) c0 = 0;
    int c1 = qt + 1; if (c1 > 15) c1 = 15;

    for (int c = c0; c <= c1; c++) {
        const int j0 = c * 128;

        const int rowlo = q0 + wid * 16;
        int ntLo = (rowlo - 127 - j0) >> 3;
        if (ntLo < 0) ntLo = 0;
        ntLo &= ~1;
        int ntHi = (rowlo + 15 + 128 - j0) >> 3;
        if (ntHi > 15) ntHi = 15;
        ntHi |= 1;
        const int kspLo = ntLo >> 1, kspHi = ntHi >> 1;

        // ---- stage K with fused RoPE ----
#pragma unroll
        for (int i = 0; i < 4; i++) {
            int idx = tid + i * 256;
            int r = idx >> 3, d4 = idx & 7;
            const float* row = kg + (size_t)(j0 + r) * HD;
            float4 a = *(const float4*)(row + d4 * 4);
            float4 b = *(const float4*)(row + d4 * 4 + 32);
            const float4 cv = *(const float4*)(g_rc + (size_t)(j0 + r) * 32 + d4 * 4);
            const float4 sn = *(const float4*)(g_rs + (size_t)(j0 + r) * 32 + d4 * 4);
            float4 lo = make_float4(a.x * cv.x - b.x * sn.x, a.y * cv.y - b.y * sn.y,
                                    a.z * cv.z - b.z * sn.z, a.w * cv.w - b.w * sn.w);
            float4 hi = make_float4(b.x * cv.x + a.x * sn.x, b.y * cv.y + a.y * sn.y,
                                    b.z * cv.z + a.z * sn.z, b.w * cv.w + a.w * sn.w);
            unsigned h0, l0, h1, l1;
            split2(lo.x, lo.y, h0, l0);
            split2(lo.z, lo.w, h1, l1);
            *(uint2*)&sv[KHI + r * 36 + d4 * 2] = make_uint2(h0, h1);
            *(uint2*)&sv[KLO + r * 36 + d4 * 2] = make_uint2(l0, l1);
            split2(hi.x, hi.y, h0, l0);
            split2(hi.z, hi.w, h1, l1);
            *(uint2*)&sv[KHI + r * 36 + (d4 + 8) * 2] = make_uint2(h0, h1);
            *(uint2*)&sv[KLO + r * 36 + (d4 + 8) * 2] = make_uint2(l0, l1);
        }
        // ---- stage V transposed: Vt[dim][keypair], stride 68 ----
#pragma unroll
        for (int i = 0; i < 4; i++) {
            int idx = tid + i * 256;
            int rp = idx >> 4, d4 = idx & 15;
            float4 va = *(const float4*)(vg + (size_t)(j0 + 2 * rp) * HD + d4 * 4);
            float4 vb = *(const float4*)(vg + (size_t)(j0 + 2 * rp + 1) * HD + d4 * 4);
            unsigned hh, ll;
            split2(va.x, vb.x, hh, ll);
            sv[VHI + (d4 * 4 + 0) * 68 + rp] = hh; sv[VLO + (d4 * 4 + 0) * 68 + rp] = ll;
            split2(va.y, vb.y, hh, ll);
            sv[VHI + (d4 * 4 + 1) * 68 + rp] = hh; sv[VLO + (d4 * 4 + 1) * 68 + rp] = ll;
            split2(va.z, vb.z, hh, ll);
            sv[VHI + (d4 * 4 + 2) * 68 + rp] = hh; sv[VLO + (d4 * 4 + 2) * 68 + rp] = ll;
            split2(va.w, vb.w, hh, ll);
            sv[VHI + (d4 * 4 + 3) * 68 + rp] = hh; sv[VLO + (d4 * 4 + 3) * 68 + rp] = ll;
        }
        __syncthreads();

        // ---- S = Q . K^T (live n-tile pairs, ldmatrix x4) ----
        float s[16][4];
#pragma unroll
        for (int nt = 0; nt < 16; nt++)
#pragma unroll
            for (int r = 0; r < 4; r++) s[nt][r] = 0.f;

#pragma unroll
        for (int ntp = 0; ntp < 8; ntp++) {
            if (ntp * 2 < ntLo || ntp * 2 > ntHi) continue;
#pragma unroll
            for (int ks = 0; ks < 4; ks++) {
                unsigned bh4[4], bl4[4];
                uint32_t base = sbase + (ntp * 16) * 144 + bRow36 + ks * 32 + bColH;
                ldsm_x4(bh4, base + KHI * 4);
                ldsm_x4(bl4, base + KLO * 4);
                mmabf(s[ntp * 2], aqh[ks], bh4);
                mmabf(s[ntp * 2], aql[ks], bh4);
                mmabf(s[ntp * 2], aqh[ks], bl4);
                mmabf(s[ntp * 2 + 1], aqh[ks], bh4 + 2);
                mmabf(s[ntp * 2 + 1], aql[ks], bh4 + 2);
                mmabf(s[ntp * 2 + 1], aqh[ks], bl4 + 2);
            }
        }

        // ---- mask + online softmax + P split-store ----
#pragma unroll
        for (int half = 0; half < 2; half++) {
            const int rowg = q0 + qr + half * 8;
            float mx = -1e30f;
#pragma unroll
            for (int nt = 0; nt < 16; nt++) {
                if (nt < ntLo || nt > ntHi) continue;
#pragma unroll
                for (int cc = 0; cc < 2; cc++) {
                    int colg = j0 + nt * 8 + t4 * 2 + cc;
                    bool valid = (colg >= rowg - 127) && (colg <= rowg + 128);
                    float v = valid ? s[nt][half * 2 + cc] * SCALE : -1e30f;
                    s[nt][half * 2 + cc] = v;
                    mx = fmaxf(mx, v);
                }
            }
            mx = fmaxf(mx, __shfl_xor_sync(0xffffffffu, mx, 1));
            mx = fmaxf(mx, __shfl_xor_sync(0xffffffffu, mx, 2));
            float mnew = fmaxf(m_i[half], mx);
            float alpha = __expf(m_i[half] - mnew);
            float sum = 0.f;
#pragma unroll
            for (int nt = 0; nt < 16; nt++) {
                if (nt < ntLo || nt > ntHi) continue;
#pragma unroll
                for (int cc = 0; cc < 2; cc++) {
                    float v = s[nt][half * 2 + cc];
                    float p = (v > -1e29f) ? __expf(v - mnew) : 0.f;
                    sum += p;
                    s[nt][half * 2 + cc] = p;
                }
            }
            sum += __shfl_xor_sync(0xffffffffu, sum, 1);
            sum += __shfl_xor_sync(0xffffffffu, sum, 2);
            l_i[half] = l_i[half] * alpha + sum;
            m_i[half] = mnew;
#pragma unroll
            for (int nt = 0; nt < 8; nt++) {
                o[nt][half * 2] *= alpha;
                o[nt][half * 2 + 1] *= alpha;
            }
            const int rloc = qr + half * 8;
#pragma unroll
            for (int nt = 0; nt < 16; nt++) {
                if (nt < ntLo || nt > ntHi) continue;
                unsigned hh, ll;
                split2(s[nt][half * 2], s[nt][half * 2 + 1], hh, ll);
                sv[PHI + rloc * 68 + nt * 4 + t4] = hh;
                sv[PLO + rloc * 68 + nt * 4 + t4] = ll;
            }
        }
        __syncwarp();

        // ---- O += P . V (live k-steps, ldmatrix x4) ----
#pragma unroll
        for (int ksp = 0; ksp < 8; ksp++) {
            if (ksp < kspLo || ksp > kspHi) continue;
            unsigned aph[4], apl[4];
            uint32_t pbase = sbase + (wid * 16) * 272 + aRow68 + ksp * 32 + aColH;
            ldsm_x4(aph, pbase + PHI * 4);
            ldsm_x4(apl, pbase + PLO * 4);
#pragma unroll
            for (int ntp = 0; ntp < 4; ntp++) {
                unsigned bh4[4], bl4[4];
                uint32_t vbase = sbase + (ntp * 16) * 272 + bRow68 + ksp * 32 + bColH;
                ldsm_x4(bh4, vbase + VHI * 4);
                ldsm_x4(bl4, vbase + VLO * 4);
                mmabf(o[ntp * 2], aph, bh4);
                mmabf(o[ntp * 2], apl, bh4);
                mmabf(o[ntp * 2], aph, bl4);
                mmabf(o[ntp * 2 + 1], aph, bh4 + 2);
                mmabf(o[ntp * 2 + 1], apl, bh4 + 2);
                mmabf(o[ntp * 2 + 1], aph, bl4 + 2);
            }
        }
        __syncthreads();
    }

    // ---- epilogue ----
#pragma unroll
    for (int half = 0; half < 2; half++) {
        const int rowg = q0 + qr + half * 8;
        const float invl = 1.f / l_i[half];
        const size_t ob = ((size_t)n * TT + rowg) * DM + h * HD;
#pragma unroll
        for (int nt = 0; nt < 8; nt++) {
            int d = nt * 8 + t4 * 2;
            *(float2*)(g_ctx + ob + d) =
                make_float2(o[nt][half * 2] * invl, o[nt][half * 2 + 1] * invl);
        }
    }
}

// ---------------------------------------------------------------------------
extern "C" void kernel_launch(void* const* d_in, const int* in_sizes, int n_in,
                              void* d_out, int out_size) {
    const float* x    = (const float*)d_in[0];   // [4,2048,512]
    const float* wqkv = (const float*)d_in[1];   // [1536,512]
    const float* outw = (const float*)d_in[2];   // [512,512]
    const float* outb = (const float*)d_in[3];   // [512]
    float* out = (float*)d_out;

    const int gemm_smem = 2 * GBUF * sizeof(unsigned);            // 61440
    const int att_smem = (PLO + 128 * 68) * sizeof(unsigned);     // 141312

    cudaFuncSetAttribute(gemm_bf<true>, cudaFuncAttributeMaxDynamicSharedMemorySize, gemm_smem);
    cudaFuncSetAttribute(gemm_bf<false>, cudaFuncAttributeMaxDynamicSharedMemorySize, gemm_smem);
    cudaFuncSetAttribute(attn_kernel, cudaFuncAttributeMaxDynamicSharedMemorySize, att_smem);

    rope_table_kernel<<<(TT * 32 + 255) / 256, 256>>>();
    gemm_bf<true><<<dim3(1536 / 64, 8192 / 128), 256, gemm_smem>>>(x, wqkv, nullptr, nullptr);
    attn_kernel<<<dim3(TT / 128, NH, NB), 256, att_smem>>>();
    gemm_bf<false><<<dim3(512 / 64, 8192 / 128), 256, gemm_smem>>>(nullptr, outw, outb, out);
}